// round 4
// baseline (speedup 1.0000x reference)
#include <cuda_runtime.h>
#include <stdint.h>

#define N_NODES 100000
#define GAMMA 0.5f
#define FIX_SCALE 8388608.0f        // 2^23
#define INV_FIX_SCALE (1.0f / 8388608.0f)
#define SMEM_NODES 57344            // 224KB of the avg table lives in smem
#define OUT_GRID 152                // one persistent block per SM (GB300 = 152 SMs)
#define OUT_BLOCK 1024

// packed per-node accumulator: high 32 = count, low 32 = fixed-point sum (2^23 scale)
__device__ unsigned long long g_pack[N_NODES];
__device__ float g_avg[N_NODES];

__global__ void zero_kernel() {
    int i = blockIdx.x * blockDim.x + threadIdx.x;
    if (i < N_NODES) g_pack[i] = 0ull;
}

__device__ __forceinline__ unsigned long long pack_edge(float m) {
    unsigned fix = __float2uint_rn(m * FIX_SCALE);
    return (1ull << 32) | (unsigned long long)fix;
}

// Scatter: one 64-bit REDG per edge carrying both count(+1) and fixed-point mask sum.
// At the REDG spread-address issue floor (~1.29 cyc/lane/SM).
__global__ void scatter_kernel(const float* __restrict__ mask,
                               const int* __restrict__ src,
                               int E) {
    int i4 = (blockIdx.x * blockDim.x + threadIdx.x) * 4;
    if (i4 + 3 < E) {
        float4 m = __ldcg(reinterpret_cast<const float4*>(mask + i4));
        int4 s = __ldcg(reinterpret_cast<const int4*>(src + i4));
        if ((unsigned)s.x < N_NODES) atomicAdd(&g_pack[s.x], pack_edge(m.x));
        if ((unsigned)s.y < N_NODES) atomicAdd(&g_pack[s.y], pack_edge(m.y));
        if ((unsigned)s.z < N_NODES) atomicAdd(&g_pack[s.z], pack_edge(m.z));
        if ((unsigned)s.w < N_NODES) atomicAdd(&g_pack[s.w], pack_edge(m.w));
    } else {
        for (int i = i4; i < E; i++) {
            int s = src[i];
            if ((unsigned)s < N_NODES) atomicAdd(&g_pack[s], pack_edge(mask[i]));
        }
    }
}

__global__ void avg_kernel() {
    int i = blockIdx.x * blockDim.x + threadIdx.x;
    if (i < N_NODES) {
        unsigned long long p = g_pack[i];
        float cnt = (float)(unsigned)(p >> 32);
        float sum = (float)(unsigned)(p & 0xffffffffull) * INV_FIX_SCALE;
        g_avg[i] = sum / fmaxf(cnt, 1.0f);
    }
}

__device__ __forceinline__ float lookup(const float* __restrict__ s_avg, int idx) {
    if ((unsigned)idx < SMEM_NODES) return s_avg[idx];     // LDS: ~conflict-degree cycles
    if ((unsigned)idx < N_NODES) return g_avg[idx];        // L1tex wavefront path
    return 0.0f;
}

// out[e] = 0.5*mask[e] + 0.25*(avg[src[e]] + avg[dst[e]])
// Persistent blocks, 224KB of the avg table staged in smem to dodge L1tex wavefronts.
__global__ void __launch_bounds__(OUT_BLOCK, 1)
out_kernel(const float* __restrict__ mask,
           const int* __restrict__ src,
           const int* __restrict__ dst,
           float* __restrict__ out,
           int E) {
    extern __shared__ float s_avg[];
    for (int i = threadIdx.x; i < SMEM_NODES; i += OUT_BLOCK)
        s_avg[i] = g_avg[i];
    __syncthreads();

    int nG = E >> 2;
    int stride = gridDim.x * OUT_BLOCK;
    for (int g = blockIdx.x * OUT_BLOCK + threadIdx.x; g < nG; g += stride) {
        int i4 = g * 4;
        float4 m = __ldcg(reinterpret_cast<const float4*>(mask + i4));
        int4 s = __ldcg(reinterpret_cast<const int4*>(src + i4));
        int4 d = __ldcg(reinterpret_cast<const int4*>(dst + i4));
        float a0 = lookup(s_avg, s.x) + lookup(s_avg, d.x);
        float a1 = lookup(s_avg, s.y) + lookup(s_avg, d.y);
        float a2 = lookup(s_avg, s.z) + lookup(s_avg, d.z);
        float a3 = lookup(s_avg, s.w) + lookup(s_avg, d.w);
        float4 o;
        o.x = (1.0f - GAMMA) * m.x + (GAMMA * 0.5f) * a0;
        o.y = (1.0f - GAMMA) * m.y + (GAMMA * 0.5f) * a1;
        o.z = (1.0f - GAMMA) * m.z + (GAMMA * 0.5f) * a2;
        o.w = (1.0f - GAMMA) * m.w + (GAMMA * 0.5f) * a3;
        __stcg(reinterpret_cast<float4*>(out + i4), o);
    }

    // tail (E % 4 leftovers)
    int tail = E & 3;
    if (blockIdx.x == 0 && (int)threadIdx.x < tail) {
        int i = (E & ~3) + threadIdx.x;
        float a = lookup(s_avg, src[i]) + lookup(s_avg, dst[i]);
        out[i] = (1.0f - GAMMA) * mask[i] + (GAMMA * 0.5f) * a;
    }
}

extern "C" void kernel_launch(void* const* d_in, const int* in_sizes, int n_in,
                              void* d_out, int out_size) {
    const float* mask = (const float*)d_in[0];
    const int* edge_index = (const int*)d_in[1];  // int32 (JAX x64 disabled)
    float* out = (float*)d_out;

    int E = in_sizes[0];
    const int* src = edge_index;       // row 0
    const int* dst = edge_index + E;   // row 1

    static bool attr_set = false;
    if (!attr_set) {
        cudaFuncSetAttribute(out_kernel, cudaFuncAttributeMaxDynamicSharedMemorySize,
                             SMEM_NODES * (int)sizeof(float));
        attr_set = true;
    }

    {
        int threads = 256;
        int blocks = (N_NODES + threads - 1) / threads;
        zero_kernel<<<blocks, threads>>>();
    }
    {
        int threads = 256;
        int work = (E + 3) / 4;
        int blocks = (work + threads - 1) / threads;
        scatter_kernel<<<blocks, threads>>>(mask, src, E);
    }
    {
        int threads = 256;
        int blocks = (N_NODES + threads - 1) / threads;
        avg_kernel<<<blocks, threads>>>();
    }
    {
        out_kernel<<<OUT_GRID, OUT_BLOCK, SMEM_NODES * sizeof(float)>>>(mask, src, dst, out, E);
    }
}